// round 2
// baseline (speedup 1.0000x reference)
#include <cuda_runtime.h>
#include <cuda_bf16.h>

// Shapes (fixed per reference setup_inputs)
#define B 2
#define S 512
#define T 512
#define D 256
#define H 128
#define BS (B*S)        // 1024
#define BT (B*T)        // 1024

// Scratch (device globals; no allocation allowed)
__device__ float g_src[BS * H];   // LN(source) @ W_su + b_su
__device__ float g_tgt[BT * H];   // LN(target) @ W_tp + b_tp
__device__ float g_A  [BS * H];   // g_src @ W1_s + b1
__device__ float g_C  [BT * H];   // g_tgt @ W1_t

// ---------------------------------------------------------------------------
// Stage 1: per-row layernorm + projection + W1_s / W1_t projection.
// One CTA per row (2048 rows total), 256 threads.
// ---------------------------------------------------------------------------
__global__ __launch_bounds__(256) void norm_proj_kernel(
    const float* __restrict__ sv, const float* __restrict__ tv,
    const float* __restrict__ sng, const float* __restrict__ snb,
    const float* __restrict__ tng, const float* __restrict__ tnb,
    const float* __restrict__ Wsu, const float* __restrict__ bsu,
    const float* __restrict__ Wtp, const float* __restrict__ btp,
    const float* __restrict__ W1,  const float* __restrict__ b1)
{
    __shared__ float xn[D];
    __shared__ float pr[H];
    __shared__ float r1[8], r2[8];

    const int r = blockIdx.x;
    const bool is_src = (r < BS);
    const int row = is_src ? r : r - BS;
    const int tid = threadIdx.x;

    const float* x    = (is_src ? sv : tv) + row * D;
    const float* gv   = is_src ? sng : tng;
    const float* bv   = is_src ? snb : tnb;
    const float* W    = is_src ? Wsu : Wtp;
    const float* bias = is_src ? bsu : btp;

    // Load one element per thread, reduce sum & sumsq
    float v = x[tid];
    float s1 = v, s2 = v * v;
    #pragma unroll
    for (int m = 16; m; m >>= 1) {
        s1 += __shfl_xor_sync(0xffffffffu, s1, m);
        s2 += __shfl_xor_sync(0xffffffffu, s2, m);
    }
    if ((tid & 31) == 0) { r1[tid >> 5] = s1; r2[tid >> 5] = s2; }
    __syncthreads();
    float t1 = 0.f, t2 = 0.f;
    #pragma unroll
    for (int i = 0; i < 8; ++i) { t1 += r1[i]; t2 += r2[i]; }
    const float mean = t1 * (1.0f / D);
    const float var  = t2 * (1.0f / D) - mean * mean;
    const float rs   = rsqrtf(var + 1e-5f);
    xn[tid] = (v - mean) * rs * gv[tid] + bv[tid];
    __syncthreads();

    // proj[h] = xn @ W[:,h] + bias[h]   (h = tid for tid < 128)
    if (tid < H) {
        float a0 = 0.f, a1 = 0.f, a2 = 0.f, a3 = 0.f;
        #pragma unroll 4
        for (int d = 0; d < D; d += 4) {
            a0 = fmaf(xn[d + 0], W[(d + 0) * H + tid], a0);
            a1 = fmaf(xn[d + 1], W[(d + 1) * H + tid], a1);
            a2 = fmaf(xn[d + 2], W[(d + 2) * H + tid], a2);
            a3 = fmaf(xn[d + 3], W[(d + 3) * H + tid], a3);
        }
        float p = (a0 + a1) + (a2 + a3) + bias[tid];
        pr[tid] = p;
        (is_src ? g_src : g_tgt)[row * H + tid] = p;
    }
    __syncthreads();

    // A/C row: proj @ W1_{s|t} (+ b1 for source)
    if (tid < H) {
        const float* Wr = W1 + (is_src ? 0 : H * H);
        float a0 = 0.f, a1 = 0.f, a2 = 0.f, a3 = 0.f;
        #pragma unroll 4
        for (int h = 0; h < H; h += 4) {
            a0 = fmaf(pr[h + 0], Wr[(h + 0) * H + tid], a0);
            a1 = fmaf(pr[h + 1], Wr[(h + 1) * H + tid], a1);
            a2 = fmaf(pr[h + 2], Wr[(h + 2) * H + tid], a2);
            a3 = fmaf(pr[h + 3], Wr[(h + 3) * H + tid], a3);
        }
        float p = (a0 + a1) + (a2 + a3) + (is_src ? b1[tid] : 0.0f);
        (is_src ? g_A : g_C)[row * H + tid] = p;
    }
}

// ---------------------------------------------------------------------------
// Stage 2: main fused kernel. One CTA per (b, s). 256 threads.
// hidden[t,k] = tgt[t,:] @ (src[s,:] .* W1_st) + A[s,k] + C[t,k]
// score[t]    = sum_k gelu(hidden[t,k]) * W2[k] + b2
// out[b,s,t]  = softsign(score) * mask[b,s]
// ---------------------------------------------------------------------------
#define TT 128   // t-tile

extern __shared__ float smem[];

__global__ __launch_bounds__(256, 1) void edge_main_kernel(
    const float* __restrict__ W1, const float* __restrict__ W2,
    const float* __restrict__ b2p, const int* __restrict__ mask,
    float* __restrict__ out)
{
    float* Wsh  = smem;                 // [H][H] scaled W1_st  (16384 f)
    float* Tsh  = smem + H * H;         // [TT][H] target tile  (16384 f)
    float* ssrc = smem + 2 * H * H;     // [H]
    float* As   = ssrc + H;             // [H]
    float* w2s  = As + H;               // [H]

    const int bs  = blockIdx.x;        // 0..1023
    const int b   = bs >> 9;
    const int tid = threadIdx.x;

    if (tid < H) {
        ssrc[tid] = g_src[bs * H + tid];
        As[tid]   = g_A[bs * H + tid];
        w2s[tid]  = W2[tid];
    }
    __syncthreads();

    // Wsh[h][k] = src[h] * W1_st[h][k]
    {
        const float4* Wst4 = (const float4*)(W1 + 2 * H * H);
        float4* Wsh4 = (float4*)Wsh;
        #pragma unroll
        for (int i = tid; i < (H * H) / 4; i += 256) {
            const int h = i >> 5;         // 32 float4 per row
            float sc = ssrc[h];
            float4 w = Wst4[i];
            w.x *= sc; w.y *= sc; w.z *= sc; w.w *= sc;
            Wsh4[i] = w;
        }
    }

    const float b2v  = b2p[0];
    const float mval = mask[bs] ? 1.0f : 0.0f;

    const int tr = (tid >> 4) * 8;   // local t base (0..120)
    const int kc = (tid & 15) * 8;   // k base (0..120)

    for (int tt = 0; tt < T / TT; ++tt) {
        const int t0 = tt * TT;
        __syncthreads();   // previous tile readers done before refill

        // Fill Tsh[t][h] = g_tgt[b, t0+t, h]
        {
            const float4* tg4 = (const float4*)(g_tgt + ((b << 9) + t0) * H);
            float4* Tsh4 = (float4*)Tsh;
            #pragma unroll
            for (int i = tid; i < (TT * H) / 4; i += 256)
                Tsh4[i] = tg4[i];
        }
        __syncthreads();

        // Mainloop: packed-f32x2 register-tiled GEMM, 8 t x 8 k per thread
        unsigned long long acc[32];
        #pragma unroll
        for (int i = 0; i < 32; ++i) acc[i] = 0ULL;

        #pragma unroll 4
        for (int h = 0; h < H; ++h) {
            unsigned long long a2[8];
            #pragma unroll
            for (int i = 0; i < 8; ++i) {
                float av = Tsh[(tr + i) * H + h];
                asm("mov.b64 %0, {%1, %1};" : "=l"(a2[i]) : "f"(av));
            }
            const ulonglong2* wp = (const ulonglong2*)(&Wsh[h * H + kc]);
            ulonglong2 w01 = wp[0];
            ulonglong2 w23 = wp[1];
            unsigned long long bb[4] = {w01.x, w01.y, w23.x, w23.y};
            #pragma unroll
            for (int i = 0; i < 8; ++i) {
                #pragma unroll
                for (int j = 0; j < 4; ++j)
                    asm("fma.rn.f32x2 %0, %1, %2, %0;"
                        : "+l"(acc[i * 4 + j]) : "l"(a2[i]), "l"(bb[j]));
            }
        }

        // Epilogue: + A + C, exact gelu, dot W2, reduce over 16 k-lanes,
        // softsign, mask, store.
        #pragma unroll
        for (int i = 0; i < 8; ++i) {
            const int t = t0 + tr + i;
            const float4 c0 = *(const float4*)(&g_C[((b << 9) + t) * H + kc]);
            const float4 c1 = *(const float4*)(&g_C[((b << 9) + t) * H + kc + 4]);
            float cc[8] = {c0.x, c0.y, c0.z, c0.w, c1.x, c1.y, c1.z, c1.w};
            float pt = 0.f;
            #pragma unroll
            for (int j2 = 0; j2 < 4; ++j2) {
                float lo, hi;
                asm("mov.b64 {%0, %1}, %2;" : "=f"(lo), "=f"(hi) : "l"(acc[i * 4 + j2]));
                {
                    const int k = kc + 2 * j2;
                    float hv = lo + As[k] + cc[2 * j2];
                    float ge = 0.5f * hv * (1.0f + erff(hv * 0.7071067811865476f));
                    pt = fmaf(ge, w2s[k], pt);
                }
                {
                    const int k = kc + 2 * j2 + 1;
                    float hv = hi + As[k] + cc[2 * j2 + 1];
                    float ge = 0.5f * hv * (1.0f + erff(hv * 0.7071067811865476f));
                    pt = fmaf(ge, w2s[k], pt);
                }
            }
            #pragma unroll
            for (int m = 8; m; m >>= 1)
                pt += __shfl_xor_sync(0xffffffffu, pt, m);
            if ((tid & 15) == 0) {
                const float sc = pt + b2v;
                const float e  = sc / (1.0f + fabsf(sc));
                out[bs * T + t] = e * mval;
            }
        }
    }
}

// ---------------------------------------------------------------------------
extern "C" void kernel_launch(void* const* d_in, const int* in_sizes, int n_in,
                              void* d_out, int out_size)
{
    const float* sv   = (const float*)d_in[0];
    const float* tv   = (const float*)d_in[1];
    const int*   mask = (const int*)d_in[2];
    const float* sng  = (const float*)d_in[3];
    const float* snb  = (const float*)d_in[4];
    const float* tng  = (const float*)d_in[5];
    const float* tnb  = (const float*)d_in[6];
    const float* Wsu  = (const float*)d_in[7];
    const float* bsu  = (const float*)d_in[8];
    const float* Wtp  = (const float*)d_in[9];
    const float* btp  = (const float*)d_in[10];
    const float* W1   = (const float*)d_in[11];
    const float* b1   = (const float*)d_in[12];
    const float* W2   = (const float*)d_in[13];
    const float* b2   = (const float*)d_in[14];
    float* out = (float*)d_out;

    norm_proj_kernel<<<BS + BT, 256>>>(sv, tv, sng, snb, tng, tnb,
                                       Wsu, bsu, Wtp, btp, W1, b1);

    const int smem_bytes = (2 * H * H + 3 * H) * (int)sizeof(float);
    cudaFuncSetAttribute(edge_main_kernel,
                         cudaFuncAttributeMaxDynamicSharedMemorySize, smem_bytes);
    edge_main_kernel<<<BS, 256, smem_bytes>>>(W1, W2, b2, mask, out);
}